// round 16
// baseline (speedup 1.0000x reference)
#include <cuda_runtime.h>
#include <cuda_bf16.h>

// BioTripletLoss: B=16384 rows, D=1024 fp32.
// pos = ||h+r-t||, neg = ||h+r-t[neg_idx]||
// dissim (rel==1): relu(0.6 - pos) + 0.5*exp(-pos)
// sim:             relu(pos - neg + 0.3) + 0.3*relu(0.1 - pos)
// out = mean over B.
//
// R16 = R13 (twice-verified champion, 31.46us) + discard.global.L2 of the
// h/r lines immediately after their values are consumed. no_allocate is
// rejected by this ptxas in BOTH createpolicy forms (R14/R15); discard is
// the remaining mechanism to keep the 128 MiB/replay h/r stream from
// churning t (the sole evict_last L2 tenant, whose cross-replay residency
// is the warm-wall advantage). h/r are read-only + single-use -> discard is
// unconditionally correct.
// Everything else byte-identical to R13: 2 rows/CTA, R7 load order, MLP=8,
// two-barrier finalize (regs 30, occ ~92%), one atomic/CTA, zero kernel node.

#define DDIM 1024
#define NTHREADS 256
#define ROWS_PER_CTA 2

static constexpr float MARGIN = 0.3f;
static constexpr float MIN_POS_DIST = 0.1f;
static constexpr float PUSH_SCALE = 2.0f;

__global__ void zero_out_kernel(float* out) {
    out[0] = 0.0f;
}

// Plain global-path 128-bit load with L2 eviction policy.
__device__ __forceinline__ float4 ld_hint4(const float4* p, unsigned long long pol) {
    float4 v;
    asm("ld.global.L2::cache_hint.v4.f32 {%0,%1,%2,%3}, [%4], %5;"
        : "=f"(v.x), "=f"(v.y), "=f"(v.z), "=f"(v.w)
        : "l"(p), "l"(pol));
    return v;
}

// Invalidate one 128B line from L2 (no writeback). Safe on read-only data.
__device__ __forceinline__ void discard_l2(const void* p) {
    asm volatile("discard.global.L2 [%0], 128;" :: "l"(p) : "memory");
}

__device__ __forceinline__ float per_sample_loss(float ps, float ns, int rel) {
    float pos_dist = sqrtf(ps);
    float neg_dist = sqrtf(ns);
    float loss;
    if (rel == 1) {
        loss = fmaxf(MARGIN * PUSH_SCALE - pos_dist, 0.0f) + 0.5f * expf(-pos_dist);
    } else {
        loss = fmaxf(pos_dist - neg_dist + MARGIN, 0.0f)
             + 0.3f * fmaxf(MIN_POS_DIST - pos_dist, 0.0f);
    }
    return loss;
}

__global__ __launch_bounds__(NTHREADS)
void triplet_loss_kernel(const float* __restrict__ h,
                         const float* __restrict__ t,
                         const float* __restrict__ r,
                         const int* __restrict__ relation_ids,
                         const int* __restrict__ neg_idx,
                         float* __restrict__ out,
                         int B) {
    const int row0 = blockIdx.x * ROWS_PER_CTA;
    const int row1 = row0 + 1;
    const int tid = threadIdx.x;

    unsigned long long pol_first, pol_last;
    asm("createpolicy.fractional.L2::evict_first.b64 %0, 1.0;" : "=l"(pol_first));
    asm("createpolicy.fractional.L2::evict_last.b64 %0, 1.0;"  : "=l"(pol_last));

    const int j0 = __ldg(&neg_idx[row0]);
    const int j1 = __ldg(&neg_idx[row1]);

    const float4* __restrict__ h4 = reinterpret_cast<const float4*>(h);
    const float4* __restrict__ r4 = reinterpret_cast<const float4*>(r);
    const float4* __restrict__ t4 = reinterpret_cast<const float4*>(t);
    const int V = DDIM / 4;  // 256 float4 per row == one per thread

    // Front-batch all 8 loads (MLP = 8), R7 ordering.
    float4 hv0 = ld_hint4(h4 + (size_t)row0 * V + tid, pol_first);
    float4 rv0 = ld_hint4(r4 + (size_t)row0 * V + tid, pol_first);
    float4 tv0 = ld_hint4(t4 + (size_t)row0 * V + tid, pol_last);
    float4 nv0 = ld_hint4(t4 + (size_t)j0   * V + tid, pol_last);
    float4 hv1 = ld_hint4(h4 + (size_t)row1 * V + tid, pol_first);
    float4 rv1 = ld_hint4(r4 + (size_t)row1 * V + tid, pol_first);
    float4 tv1 = ld_hint4(t4 + (size_t)row1 * V + tid, pol_last);
    float4 nv1 = ld_hint4(t4 + (size_t)j1   * V + tid, pol_last);

    float hx, hy, hz, hw, d;

    // Row 0
    hx = hv0.x + rv0.x; hy = hv0.y + rv0.y; hz = hv0.z + rv0.z; hw = hv0.w + rv0.w;
    float ps0 = 0.0f, ns0 = 0.0f;
    d = hx - tv0.x; ps0 += d*d;  d = hy - tv0.y; ps0 += d*d;
    d = hz - tv0.z; ps0 += d*d;  d = hw - tv0.w; ps0 += d*d;
    d = hx - nv0.x; ns0 += d*d;  d = hy - nv0.y; ns0 += d*d;
    d = hz - nv0.z; ns0 += d*d;  d = hw - nv0.w; ns0 += d*d;

    // Row 1
    hx = hv1.x + rv1.x; hy = hv1.y + rv1.y; hz = hv1.z + rv1.z; hw = hv1.w + rv1.w;
    float ps1 = 0.0f, ns1 = 0.0f;
    d = hx - tv1.x; ps1 += d*d;  d = hy - tv1.y; ps1 += d*d;
    d = hz - tv1.z; ps1 += d*d;  d = hw - tv1.w; ps1 += d*d;
    d = hx - nv1.x; ns1 += d*d;  d = hy - nv1.y; ns1 += d*d;
    d = hz - nv1.z; ns1 += d*d;  d = hw - nv1.w; ns1 += d*d;

    // h/r values fully consumed -> discard their L2 lines (one lane per
    // 128B line: 8 consecutive tids share a line of 8 float4s).
    if ((tid & 7) == 0) {
        const int base = tid;  // line-aligned float4 index
        discard_l2(h4 + (size_t)row0 * V + base);
        discard_l2(r4 + (size_t)row0 * V + base);
        discard_l2(h4 + (size_t)row1 * V + base);
        discard_l2(r4 + (size_t)row1 * V + base);
    }

    // Warp reduce all four accumulators
    #pragma unroll
    for (int off = 16; off > 0; off >>= 1) {
        ps0 += __shfl_xor_sync(0xFFFFFFFFu, ps0, off);
        ns0 += __shfl_xor_sync(0xFFFFFFFFu, ns0, off);
        ps1 += __shfl_xor_sync(0xFFFFFFFFu, ps1, off);
        ns1 += __shfl_xor_sync(0xFFFFFFFFu, ns1, off);
    }

    // Block reduce across 8 warps (two-barrier finalize: regs stay low)
    __shared__ float s_ps0[NTHREADS / 32], s_ns0[NTHREADS / 32];
    __shared__ float s_ps1[NTHREADS / 32], s_ns1[NTHREADS / 32];
    __shared__ float s_loss1;
    const int lane = tid & 31;
    const int wid = tid >> 5;
    if (lane == 0) {
        s_ps0[wid] = ps0; s_ns0[wid] = ns0;
        s_ps1[wid] = ps1; s_ns1[wid] = ns1;
    }
    __syncthreads();

    // Warp 1 finalizes row 1 into smem; warp 0 finalizes row 0 and issues the
    // CTA's single atomic after a second barrier.
    if (tid == 32) {
        float ps = 0.0f, ns = 0.0f;
        #pragma unroll
        for (int w = 0; w < NTHREADS / 32; w++) { ps += s_ps1[w]; ns += s_ns1[w]; }
        s_loss1 = per_sample_loss(ps, ns, __ldg(&relation_ids[row1]));
    }
    __syncthreads();
    if (tid == 0) {
        float ps = 0.0f, ns = 0.0f;
        #pragma unroll
        for (int w = 0; w < NTHREADS / 32; w++) { ps += s_ps0[w]; ns += s_ns0[w]; }
        float loss = per_sample_loss(ps, ns, __ldg(&relation_ids[row0])) + s_loss1;
        atomicAdd(out, loss * (1.0f / (float)B));
    }
}

extern "C" void kernel_launch(void* const* d_in, const int* in_sizes, int n_in,
                              void* d_out, int out_size) {
    const float* h = (const float*)d_in[0];
    const float* t = (const float*)d_in[1];
    const float* r = (const float*)d_in[2];
    const int* relation_ids = (const int*)d_in[3];
    const int* neg_idx = (const int*)d_in[4];
    float* out = (float*)d_out;

    const int B = in_sizes[3];  // element count of relation_ids

    zero_out_kernel<<<1, 1>>>(out);
    triplet_loss_kernel<<<B / ROWS_PER_CTA, NTHREADS>>>(h, t, r, relation_ids, neg_idx, out, B);
}

// round 17
// speedup vs baseline: 6.1012x; 6.1012x over previous
#include <cuda_runtime.h>
#include <cuda_bf16.h>

// BioTripletLoss: B=16384 rows, D=1024 fp32.
// pos = ||h+r-t||, neg = ||h+r-t[neg_idx]||
// dissim (rel==1): relu(0.6 - pos) + 0.5*exp(-pos)
// sim:             relu(pos - neg + 0.3) + 0.3*relu(0.1 - pos)
// out = mean over B.
//
// FINAL (R17) = exact R13/R7, the measured + twice-verified champion
// (31.49 / 31.46 us; 41.7 us naive baseline -> 1.33x):
//  - 2 rows/CTA, 256 threads, one float4/thread/stream, 8 front-batched
//    plain-global cache_hint loads (MLP=8), R7 order (h,r,t,neg per row).
//  - L2 policy: h, r -> evict_first (single-use streams); t -> evict_last
//    (SOLE retention tenant; steady-state residency across graph replays
//    is worth ~3-4us of wall — R11 proved adding h displaces it).
//  - Two-barrier finalize (warp1 -> smem -> warp0): keeps regs at 30 and
//    occupancy ~92%; single-barrier variant costs 4 regs / ~1.1us (R12).
//  - One atomicAdd per CTA; separate 1-thread zero kernel node (R8's
//    fence-based finalize and R9's memset node were worse/equal).
// Rejected by measurement: R5 extra MLP, R6 persistent grid, R10 gather-first
// reorder, R11 h-retention, R12 single barrier, R14/R15 no_allocate (ptxas),
// R16 discard.global.L2 (6x regression — serializing L2 op on sm_103a).

#define DDIM 1024
#define NTHREADS 256
#define ROWS_PER_CTA 2

static constexpr float MARGIN = 0.3f;
static constexpr float MIN_POS_DIST = 0.1f;
static constexpr float PUSH_SCALE = 2.0f;

__global__ void zero_out_kernel(float* out) {
    out[0] = 0.0f;
}

// Plain global-path 128-bit load with L2 eviction policy (no .nc).
__device__ __forceinline__ float4 ld_hint4(const float4* p, unsigned long long pol) {
    float4 v;
    asm("ld.global.L2::cache_hint.v4.f32 {%0,%1,%2,%3}, [%4], %5;"
        : "=f"(v.x), "=f"(v.y), "=f"(v.z), "=f"(v.w)
        : "l"(p), "l"(pol));
    return v;
}

__device__ __forceinline__ float per_sample_loss(float ps, float ns, int rel) {
    float pos_dist = sqrtf(ps);
    float neg_dist = sqrtf(ns);
    float loss;
    if (rel == 1) {
        loss = fmaxf(MARGIN * PUSH_SCALE - pos_dist, 0.0f) + 0.5f * expf(-pos_dist);
    } else {
        loss = fmaxf(pos_dist - neg_dist + MARGIN, 0.0f)
             + 0.3f * fmaxf(MIN_POS_DIST - pos_dist, 0.0f);
    }
    return loss;
}

__global__ __launch_bounds__(NTHREADS)
void triplet_loss_kernel(const float* __restrict__ h,
                         const float* __restrict__ t,
                         const float* __restrict__ r,
                         const int* __restrict__ relation_ids,
                         const int* __restrict__ neg_idx,
                         float* __restrict__ out,
                         int B) {
    const int row0 = blockIdx.x * ROWS_PER_CTA;
    const int row1 = row0 + 1;
    const int tid = threadIdx.x;

    unsigned long long pol_first, pol_last;
    asm("createpolicy.fractional.L2::evict_first.b64 %0, 1.0;" : "=l"(pol_first));
    asm("createpolicy.fractional.L2::evict_last.b64 %0, 1.0;"  : "=l"(pol_last));

    const int j0 = __ldg(&neg_idx[row0]);
    const int j1 = __ldg(&neg_idx[row1]);

    const float4* __restrict__ h4 = reinterpret_cast<const float4*>(h);
    const float4* __restrict__ r4 = reinterpret_cast<const float4*>(r);
    const float4* __restrict__ t4 = reinterpret_cast<const float4*>(t);
    const int V = DDIM / 4;  // 256 float4 per row == one per thread

    // Front-batch all 8 loads (MLP = 8).
    float4 hv0 = ld_hint4(h4 + (size_t)row0 * V + tid, pol_first);
    float4 rv0 = ld_hint4(r4 + (size_t)row0 * V + tid, pol_first);
    float4 tv0 = ld_hint4(t4 + (size_t)row0 * V + tid, pol_last);
    float4 nv0 = ld_hint4(t4 + (size_t)j0   * V + tid, pol_last);
    float4 hv1 = ld_hint4(h4 + (size_t)row1 * V + tid, pol_first);
    float4 rv1 = ld_hint4(r4 + (size_t)row1 * V + tid, pol_first);
    float4 tv1 = ld_hint4(t4 + (size_t)row1 * V + tid, pol_last);
    float4 nv1 = ld_hint4(t4 + (size_t)j1   * V + tid, pol_last);

    float hx, hy, hz, hw, d;

    // Row 0
    hx = hv0.x + rv0.x; hy = hv0.y + rv0.y; hz = hv0.z + rv0.z; hw = hv0.w + rv0.w;
    float ps0 = 0.0f, ns0 = 0.0f;
    d = hx - tv0.x; ps0 += d*d;  d = hy - tv0.y; ps0 += d*d;
    d = hz - tv0.z; ps0 += d*d;  d = hw - tv0.w; ps0 += d*d;
    d = hx - nv0.x; ns0 += d*d;  d = hy - nv0.y; ns0 += d*d;
    d = hz - nv0.z; ns0 += d*d;  d = hw - nv0.w; ns0 += d*d;

    // Row 1
    hx = hv1.x + rv1.x; hy = hv1.y + rv1.y; hz = hv1.z + rv1.z; hw = hv1.w + rv1.w;
    float ps1 = 0.0f, ns1 = 0.0f;
    d = hx - tv1.x; ps1 += d*d;  d = hy - tv1.y; ps1 += d*d;
    d = hz - tv1.z; ps1 += d*d;  d = hw - tv1.w; ps1 += d*d;
    d = hx - nv1.x; ns1 += d*d;  d = hy - nv1.y; ns1 += d*d;
    d = hz - nv1.z; ns1 += d*d;  d = hw - nv1.w; ns1 += d*d;

    // Warp reduce all four accumulators
    #pragma unroll
    for (int off = 16; off > 0; off >>= 1) {
        ps0 += __shfl_xor_sync(0xFFFFFFFFu, ps0, off);
        ns0 += __shfl_xor_sync(0xFFFFFFFFu, ns0, off);
        ps1 += __shfl_xor_sync(0xFFFFFFFFu, ps1, off);
        ns1 += __shfl_xor_sync(0xFFFFFFFFu, ns1, off);
    }

    // Block reduce across 8 warps (two-barrier finalize: regs stay at 30)
    __shared__ float s_ps0[NTHREADS / 32], s_ns0[NTHREADS / 32];
    __shared__ float s_ps1[NTHREADS / 32], s_ns1[NTHREADS / 32];
    __shared__ float s_loss1;
    const int lane = tid & 31;
    const int wid = tid >> 5;
    if (lane == 0) {
        s_ps0[wid] = ps0; s_ns0[wid] = ns0;
        s_ps1[wid] = ps1; s_ns1[wid] = ns1;
    }
    __syncthreads();

    // Warp 1 finalizes row 1 into smem; warp 0 finalizes row 0 and issues the
    // CTA's single atomic after a second barrier.
    if (tid == 32) {
        float ps = 0.0f, ns = 0.0f;
        #pragma unroll
        for (int w = 0; w < NTHREADS / 32; w++) { ps += s_ps1[w]; ns += s_ns1[w]; }
        s_loss1 = per_sample_loss(ps, ns, __ldg(&relation_ids[row1]));
    }
    __syncthreads();
    if (tid == 0) {
        float ps = 0.0f, ns = 0.0f;
        #pragma unroll
        for (int w = 0; w < NTHREADS / 32; w++) { ps += s_ps0[w]; ns += s_ns0[w]; }
        float loss = per_sample_loss(ps, ns, __ldg(&relation_ids[row0])) + s_loss1;
        atomicAdd(out, loss * (1.0f / (float)B));
    }
}

extern "C" void kernel_launch(void* const* d_in, const int* in_sizes, int n_in,
                              void* d_out, int out_size) {
    const float* h = (const float*)d_in[0];
    const float* t = (const float*)d_in[1];
    const float* r = (const float*)d_in[2];
    const int* relation_ids = (const int*)d_in[3];
    const int* neg_idx = (const int*)d_in[4];
    float* out = (float*)d_out;

    const int B = in_sizes[3];  // element count of relation_ids

    zero_out_kernel<<<1, 1>>>(out);
    triplet_loss_kernel<<<B / ROWS_PER_CTA, NTHREADS>>>(h, t, r, relation_ids, neg_idx, out, B);
}